// round 2
// baseline (speedup 1.0000x reference)
#include <cuda_runtime.h>
#include <cstdint>
#include <cstddef>

// Problem constants
#define TM      128     // rows per CTA
#define KC      32      // k-chunk
#define NT      256     // threads per CTA
#define LATENT  256
#define NNODES  256
#define NROWS   65536
#define ZS_STRIDE 132   // floats, mult of 4 -> 16B-aligned LDS.128 for every k
#define ES2S    256     // u64 stride for duplicated-pair E tile
#define REDS    33      // padded reduction stride (conflict-free)
#define EPSF    1.1920929e-7f

typedef unsigned long long u64;

// Packed 2-wide fp32 FMA (FFMA2) — PTX-only on sm_103a, 2x FFMA throughput.
__device__ __forceinline__ u64 ffma2(u64 a, u64 b, u64 c) {
    u64 d;
    asm("fma.rn.f32x2 %0, %1, %2, %3;" : "=l"(d) : "l"(a), "l"(b), "l"(c));
    return d;
}
__device__ __forceinline__ u64 pack2(float x) {
    u64 d;
    asm("mov.b64 %0, {%1, %1};" : "=l"(d) : "f"(x));
    return d;
}

extern __shared__ float smf[];

// shared layout (floats):
//   union region [0 .. 20608):
//     GEMM phase: zs  = [0 .. 4224)                 (KC * 132)
//                 es2 = [4224 .. 20608)             (KC * 256 u64 = 16384 floats)
//     RED  phase: redv = [0 .. 4224)                (128*33)
//                 redi = [4224 .. 8448)
//                 reds = [8448 .. 12672)
//   persistent  [20608 .. 21248): e2(256) z2(128) bmu(128) rqs(128)
#define UNION_FLOATS 20608
#define SMEM_FLOATS  (UNION_FLOATS + 256 + 128 + 128 + 128)
#define SMEM_BYTES   (SMEM_FLOATS * 4)

__global__ void __launch_bounds__(NT, 1)
som_kernel(const float* __restrict__ Z, const float* __restrict__ E,
           const int* __restrict__ Alpha, float* __restrict__ out)
{
    float* zs   = smf;                          // GEMM phase
    u64*   es2  = (u64*)(smf + KC * ZS_STRIDE); // GEMM phase (8B aligned: 4224*4=16896)
    float* redv = smf;                          // RED phase (overlays zs/es2)
    int*   redi = (int*)(smf + TM * REDS);
    float* reds = smf + 2 * TM * REDS;
    float* e2   = smf + UNION_FLOATS;
    float* z2   = e2 + NNODES;
    int*   bmuS = (int*)(z2 + TM);
    float* rqs  = (float*)(bmuS + TM);

    const int t  = threadIdx.x;
    const int R0 = blockIdx.x * TM;
    const int cg = t & 31;          // node lane: owns nodes {cg, cg+32, ..., cg+224}
    const int rg = t >> 5;          // row group (16 rows)
    const int r0 = rg * 16;

    // ---- e2[j] = ||e_j||^2 (one node per thread), z2[r] for this tile ----
    {
        const float4* er = (const float4*)(E + (size_t)t * LATENT);
        float s = 0.f;
        #pragma unroll 8
        for (int i = 0; i < 64; i++) { float4 v = er[i]; s += v.x*v.x + v.y*v.y + v.z*v.z + v.w*v.w; }
        e2[t] = s;
    }
    if (t < TM) {
        const float4* zr = (const float4*)(Z + (size_t)(R0 + t) * LATENT);
        float s = 0.f;
        #pragma unroll 8
        for (int i = 0; i < 64; i++) { float4 v = zr[i]; s += v.x*v.x + v.y*v.y + v.z*v.z + v.w*v.w; }
        z2[t] = s;
    }

    // ---- GEMM: dot[r][j], per-thread 16 rows (8 f32x2 pairs) x 8 nodes ----
    u64 acc[8][8];
    #pragma unroll
    for (int p = 0; p < 8; p++)
        #pragma unroll
        for (int n = 0; n < 8; n++) acc[p][n] = 0ull;

    for (int c = 0; c < LATENT; c += KC) {
        __syncthreads();   // previous chunk's compute done before smem overwrite
        // z tile: 128 rows x KC, stored transposed zs[k][row]
        #pragma unroll
        for (int i = 0; i < 4; i++) {
            int v = t + NT * i;
            int row = v >> 3, kq = v & 7;
            float4 zv = *(const float4*)(Z + (size_t)(R0 + row) * LATENT + c + kq * 4);
            float* p0 = zs + (kq * 4) * ZS_STRIDE + row;
            p0[0]             = zv.x;
            p0[ZS_STRIDE]     = zv.y;
            p0[2 * ZS_STRIDE] = zv.z;
            p0[3 * ZS_STRIDE] = zv.w;
        }
        // e tile: thread t = node t, stored transposed + DUPLICATED pairs es2[k][node]={e,e}
        {
            const float4* er = (const float4*)(E + (size_t)t * LATENT + c);
            #pragma unroll
            for (int j = 0; j < 8; j++) {
                float4 ev = er[j];
                u64* p0 = es2 + (size_t)(j * 4) * ES2S + t;
                p0[0]        = pack2(ev.x);
                p0[ES2S]     = pack2(ev.y);
                p0[2 * ES2S] = pack2(ev.z);
                p0[3 * ES2S] = pack2(ev.w);
            }
        }
        __syncthreads();
        #pragma unroll 4
        for (int k = 0; k < KC; k++) {
            // z rows: 4x LDS.128, broadcast within warp (all lanes same addr)
            const ulonglong2* zp = (const ulonglong2*)(zs + k * ZS_STRIDE + r0);
            ulonglong2 za = zp[0], zb = zp[1], zc = zp[2], zd = zp[3];
            u64 zf[8] = { za.x, za.y, zb.x, zb.y, zc.x, zc.y, zd.x, zd.y };
            // e nodes: 8x LDS.64, lane-contiguous u64 -> conflict-free
            const u64* ep = es2 + (size_t)k * ES2S + cg;
            u64 ef[8];
            #pragma unroll
            for (int n = 0; n < 8; n++) ef[n] = ep[n * 32];
            #pragma unroll
            for (int n = 0; n < 8; n++)
                #pragma unroll
                for (int p2 = 0; p2 < 8; p2++)
                    acc[p2][n] = ffma2(zf[p2], ef[n], acc[p2][n]);
        }
    }
    __syncthreads();   // GEMM smem region now reusable for reductions

    // ---- alpha (robust to int32/int64-low-word/float32 encodings) ----
    int ai = Alpha[0];
    float a = (ai > 0 && ai < 1000000) ? (float)ai : __int_as_float(ai);
    float inva = 1.0f / a;
    float coef = -(a + 1.0f) * 0.5f;

    // ---- per-(row, node) d, q; per-row local argmin (strict <) + qsum ----
    float rmin[16], rsum[16];
    int   rid[16];
    #pragma unroll
    for (int i = 0; i < 16; i++) { rmin[i] = 3.4e38f; rsum[i] = 0.f; rid[i] = 0; }

    #pragma unroll
    for (int p = 0; p < 8; p++) {
        float z2l = z2[r0 + 2 * p], z2h = z2[r0 + 2 * p + 1];
        #pragma unroll
        for (int n = 0; n < 8; n++) {
            int j = n * 32 + cg;
            float e2j = e2[j];
            u64 av = acc[p][n];
            float dotl = __uint_as_float((unsigned)av);
            float doth = __uint_as_float((unsigned)(av >> 32));
            float dl = fmaxf(z2l + e2j - 2.f * dotl, 0.f);
            float dh = fmaxf(z2h + e2j - 2.f * doth, 0.f);
            float ql = exp2f(coef * __log2f(fmaf(dl, inva, 1.0f)));
            float qh = exp2f(coef * __log2f(fmaf(dh, inva, 1.0f)));
            if (dl < rmin[2 * p])     { rmin[2 * p]     = dl; rid[2 * p]     = j; }
            if (dh < rmin[2 * p + 1]) { rmin[2 * p + 1] = dh; rid[2 * p + 1] = j; }
            rsum[2 * p]     += ql;
            rsum[2 * p + 1] += qh;
            // reuse accumulator registers to hold raw q (lo,hi packed)
            acc[p][n] = ((u64)__float_as_uint(qh) << 32) | (u64)__float_as_uint(ql);
        }
    }
    #pragma unroll
    for (int i = 0; i < 16; i++) {
        int row = r0 + i;
        redv[row * REDS + cg] = rmin[i];
        redi[row * REDS + cg] = rid[i];
        reds[row * REDS + cg] = rsum[i];
    }
    __syncthreads();

    // ---- cross-column reduction: bmu + 1/qsum per row ----
    if (t < TM) {
        float bv = 3.4e38f; int bi = 0; float s = 0.f;
        #pragma unroll 4
        for (int g = 0; g < 32; g++) {
            float v = redv[t * REDS + g];
            s += reds[t * REDS + g];
            if (v < bv) { bv = v; bi = redi[t * REDS + g]; }
        }
        bmuS[t] = bi;
        rqs[t]  = 1.0f / s;
    }
    __syncthreads();

    // ---- output layout (floats): [z_q | z_q_neighbors | q | bmu] ----
    const size_t NBOFF  = (size_t)NROWS * 256;
    const size_t QOFF   = (size_t)NROWS * 1536;
    const size_t BMUOFF = (size_t)NROWS * 1792;

    // q = qraw/sum + eps  (per n: lanes write contiguous floats -> coalesced)
    #pragma unroll
    for (int p = 0; p < 8; p++) {
        #pragma unroll
        for (int h = 0; h < 2; h++) {
            int row = r0 + 2 * p + h;
            float rq = rqs[row];
            float* dst = out + QOFF + (size_t)(R0 + row) * NNODES + cg;
            #pragma unroll
            for (int n = 0; n < 8; n++) {
                u64 av = acc[p][n];
                unsigned bits = h ? (unsigned)(av >> 32) : (unsigned)av;
                dst[n * 32] = fmaf(__uint_as_float(bits), rq, EPSF);
            }
        }
    }

    // bmu (as float value)
    if (t < TM) out[BMUOFF + R0 + t] = (float)bmuS[t];

    // z_q + neighbor gathers: 6 row-copies per row, one warp per copy
    const int lane = t & 31, wid = t >> 5;
    for (int cp = wid; cp < TM * 6; cp += 8) {
        int row = cp / 6;
        int s   = cp - row * 6;
        int b   = bmuS[row];
        int idx;
        if (s <= 1) {
            idx = b;                                    // z_q, neighbors[0]=self
        } else {
            int k1 = b >> 4, k2 = b & 15;
            if      (s == 2) idx = (((k1 + 15) & 15) << 4) + k2;   // up
            else if (s == 3) idx = (((k1 + 1)  & 15) << 4) + k2;   // down
            else if (s == 4) idx = (k1 << 4) + ((k2 + 1)  & 15);   // right
            else             idx = (k1 << 4) + ((k2 + 15) & 15);   // left
        }
        const float4* src = (const float4*)(E + (size_t)idx * LATENT);
        float4 a0 = src[lane], a1 = src[lane + 32];
        float* dstp = (s == 0)
            ? out + (size_t)(R0 + row) * LATENT
            : out + NBOFF + ((size_t)(R0 + row) * 5 + (s - 1)) * LATENT;
        float4* d4 = (float4*)dstp;
        d4[lane]      = a0;
        d4[lane + 32] = a1;
    }
}

extern "C" void kernel_launch(void* const* d_in, const int* in_sizes, int n_in,
                              void* d_out, int out_size) {
    const float* Z = (const float*)d_in[0];
    const float* E = (const float*)d_in[1];
    const int*   A = (const int*)d_in[2];
    float* out = (float*)d_out;

    cudaFuncSetAttribute(som_kernel, cudaFuncAttributeMaxDynamicSharedMemorySize, SMEM_BYTES);
    som_kernel<<<NROWS / TM, NT, SMEM_BYTES>>>(Z, E, A, out);
}

// round 3
// speedup vs baseline: 1.1586x; 1.1586x over previous
#include <cuda_runtime.h>
#include <cstdint>
#include <cstddef>

#define TM      128     // rows per CTA
#define NT      512     // threads per CTA (16 warps)
#define KC      32      // k-chunk
#define LATENT  256
#define NNODES  256
#define NROWS   65536
#define ZS_STRIDE 132   // floats (16B-aligned rows for LDS.128)
#define ES_STRIDE 258   // floats (even -> 8B-aligned node-pair LDS.64)
#define STAGE_FLOATS (KC*ZS_STRIDE + KC*ES_STRIDE)   // 4224 + 8256 = 12480
#define REDS    33
#define EPSF    1.1920929e-7f

typedef unsigned long long u64;

__device__ __forceinline__ u64 ffma2(u64 a, u64 b, u64 c) {
    u64 d;
    asm("fma.rn.f32x2 %0, %1, %2, %3;" : "=l"(d) : "l"(a), "l"(b), "l"(c));
    return d;
}
__device__ __forceinline__ u64 pack2(float x) {
    u64 d;
    asm("mov.b64 %0, {%1, %1};" : "=l"(d) : "f"(x));
    return d;
}
__device__ __forceinline__ u64 packf2(float lo, float hi) {
    u64 d;
    asm("mov.b64 %0, {%1, %2};" : "=l"(d) : "f"(lo), "f"(hi));
    return d;
}

extern __shared__ float smf[];

// smem: two GEMM stages [0 .. 2*12480) ; persistent tail: e2(256) z2(128) bmu(128) rqs(128)
// reduction arrays overlay the (then-dead) stage region after the GEMM.
#define SMEM_FLOATS (2*STAGE_FLOATS + 256 + 128 + 128 + 128)
#define SMEM_BYTES  (SMEM_FLOATS * 4)

__global__ void __launch_bounds__(NT, 1)
som_kernel(const float* __restrict__ Z, const float* __restrict__ E,
           const int* __restrict__ Alpha, float* __restrict__ out)
{
    float* e2   = smf + 2 * STAGE_FLOATS;
    float* z2   = e2 + NNODES;
    int*   bmuS = (int*)(z2 + TM);
    float* rqs  = (float*)(bmuS + TM);
    float* redv = smf;                       // overlays stage0 (dead post-GEMM)
    int*   redi = (int*)(smf + TM * REDS);
    float* reds = smf + 2 * TM * REDS;

    const int t  = threadIdx.x;
    const int R0 = blockIdx.x * TM;
    const int cg = t & 31;       // node lane: pairs {cg, cg+32, cg+64, cg+96} -> nodes 2*np, 2*np+1
    const int rg = t >> 5;       // 16 row groups of 8 rows
    const int r0 = rg * 8;

    // ---- e2[j] = ||e_j||^2 (L2-resident read) ----
    if (t < NNODES) {
        const float4* er4 = (const float4*)(E + (size_t)t * LATENT);
        float s = 0.f;
        #pragma unroll 8
        for (int i = 0; i < 64; i++) { float4 v = er4[i]; s += v.x*v.x + v.y*v.y + v.z*v.z + v.w*v.w; }
        e2[t] = s;
    }

    // ---- prefetch mapping (constant per thread) ----
    // Z: 2 float4/thread/chunk, coalesced per row
    const int zv0 = t, zv1 = t + NT;
    const int zrow0 = zv0 >> 3, zkq0 = zv0 & 7;
    const int zrow1 = zv1 >> 3, zkq1 = zv1 & 7;
    // E: 4 float4/thread/chunk, lane-per-node (uncoalesced 16B, L2-resident)
    int enode[4], ekq[4];
    #pragma unroll
    for (int i = 0; i < 4; i++) { int v = t + NT * i; enode[i] = v & 255; ekq[i] = v >> 8; }

    u64 acc[8][4];
    #pragma unroll
    for (int r = 0; r < 8; r++)
        #pragma unroll
        for (int m = 0; m < 4; m++) acc[r][m] = 0ull;

    // prologue: load chunk 0 into registers
    float4 zr0 = *(const float4*)(Z + (size_t)(R0 + zrow0) * LATENT + zkq0 * 4);
    float4 zr1 = *(const float4*)(Z + (size_t)(R0 + zrow1) * LATENT + zkq1 * 4);
    float4 er[4];
    #pragma unroll
    for (int i = 0; i < 4; i++)
        er[i] = *(const float4*)(E + (size_t)enode[i] * LATENT + ekq[i] * 4);

    float z2r = 0.f;   // per-row ||z||^2, accumulated from smem tiles (t < TM owns row t)

    for (int c = 0; c < LATENT / KC; c++) {
        float* zs = smf + (c & 1) * STAGE_FLOATS;
        float* es = zs + KC * ZS_STRIDE;

        // store prefetched regs -> this stage
        {
            float* p = zs + (4 * zkq0) * ZS_STRIDE + zrow0;
            p[0] = zr0.x; p[ZS_STRIDE] = zr0.y; p[2*ZS_STRIDE] = zr0.z; p[3*ZS_STRIDE] = zr0.w;
            p = zs + (4 * zkq1) * ZS_STRIDE + zrow1;
            p[0] = zr1.x; p[ZS_STRIDE] = zr1.y; p[2*ZS_STRIDE] = zr1.z; p[3*ZS_STRIDE] = zr1.w;
            #pragma unroll
            for (int i = 0; i < 4; i++) {
                float* q = es + (4 * ekq[i]) * ES_STRIDE + enode[i];
                q[0] = er[i].x; q[ES_STRIDE] = er[i].y; q[2*ES_STRIDE] = er[i].z; q[3*ES_STRIDE] = er[i].w;
            }
        }
        __syncthreads();

        // issue next chunk's loads (latency hidden behind compute below)
        if (c < LATENT / KC - 1) {
            int cb = (c + 1) * KC;
            zr0 = *(const float4*)(Z + (size_t)(R0 + zrow0) * LATENT + cb + zkq0 * 4);
            zr1 = *(const float4*)(Z + (size_t)(R0 + zrow1) * LATENT + cb + zkq1 * 4);
            #pragma unroll
            for (int i = 0; i < 4; i++)
                er[i] = *(const float4*)(E + (size_t)enode[i] * LATENT + cb + ekq[i] * 4);
        }

        // z2 partial from this chunk's tile (thread t owns row t)
        if (t < TM) {
            #pragma unroll 8
            for (int k = 0; k < KC; k++) { float v = zs[k * ZS_STRIDE + t]; z2r = fmaf(v, v, z2r); }
        }

        // inner GEMM: 8 rows x 4 node-pairs per thread
        #pragma unroll 2
        for (int k = 0; k < KC; k++) {
            const float4* zp4 = (const float4*)(zs + k * ZS_STRIDE + r0);
            float4 za = zp4[0], zb = zp4[1];
            u64 zp[8] = { pack2(za.x), pack2(za.y), pack2(za.z), pack2(za.w),
                          pack2(zb.x), pack2(zb.y), pack2(zb.z), pack2(zb.w) };
            const float* ek = es + k * ES_STRIDE + 2 * cg;
            u64 ef0 = *(const u64*)(ek);
            u64 ef1 = *(const u64*)(ek + 64);
            u64 ef2 = *(const u64*)(ek + 128);
            u64 ef3 = *(const u64*)(ek + 192);
            #pragma unroll
            for (int r = 0; r < 8; r++) {
                acc[r][0] = ffma2(zp[r], ef0, acc[r][0]);
                acc[r][1] = ffma2(zp[r], ef1, acc[r][1]);
                acc[r][2] = ffma2(zp[r], ef2, acc[r][2]);
                acc[r][3] = ffma2(zp[r], ef3, acc[r][3]);
            }
        }
        __syncthreads();
    }

    if (t < TM) z2[t] = z2r;
    __syncthreads();   // z2 visible; stages dead -> reduction overlay safe

    // ---- alpha ----
    int ai = Alpha[0];
    float a = (ai > 0 && ai < 1000000) ? (float)ai : __int_as_float(ai);
    float inva = 1.0f / a;
    float coef = -(a + 1.0f) * 0.5f;

    // ---- epilogue: d, q, per-row local argmin + qsum ----
    float rmin[8], rsum[8];
    int   rid[8];
    #pragma unroll
    for (int r = 0; r < 8; r++) { rmin[r] = 3.4e38f; rsum[r] = 0.f; rid[r] = 0; }

    float z2v[8];
    #pragma unroll
    for (int r = 0; r < 8; r++) z2v[r] = z2[r0 + r];

    #pragma unroll
    for (int m = 0; m < 4; m++) {
        int j0 = 2 * cg + 64 * m, j1 = j0 + 1;
        float e20 = e2[j0], e21 = e2[j1];
        #pragma unroll
        for (int r = 0; r < 8; r++) {
            u64 av = acc[r][m];
            float dotl = __uint_as_float((unsigned)av);
            float doth = __uint_as_float((unsigned)(av >> 32));
            float dl = fmaxf(z2v[r] + e20 - 2.f * dotl, 0.f);
            float dh = fmaxf(z2v[r] + e21 - 2.f * doth, 0.f);
            float ql = exp2f(coef * __log2f(fmaf(dl, inva, 1.0f)));
            float qh = exp2f(coef * __log2f(fmaf(dh, inva, 1.0f)));
            if (dl < rmin[r]) { rmin[r] = dl; rid[r] = j0; }
            if (dh < rmin[r]) { rmin[r] = dh; rid[r] = j1; }
            rsum[r] += ql + qh;
            acc[r][m] = packf2(ql, qh);   // stash raw q
        }
    }
    #pragma unroll
    for (int r = 0; r < 8; r++) {
        int row = r0 + r;
        redv[row * REDS + cg] = rmin[r];
        redi[row * REDS + cg] = rid[r];
        reds[row * REDS + cg] = rsum[r];
    }
    __syncthreads();

    // ---- cross-lane reduction: bmu (lowest-index tie-break) + 1/qsum ----
    if (t < TM) {
        float bv = 3.4e38f; int bi = 0x7fffffff; float s = 0.f;
        #pragma unroll 4
        for (int g = 0; g < 32; g++) {
            float v = redv[t * REDS + g];
            int   i = redi[t * REDS + g];
            s += reds[t * REDS + g];
            if (v < bv || (v == bv && i < bi)) { bv = v; bi = i; }
        }
        bmuS[t] = bi;
        rqs[t]  = 1.0f / s;
    }
    __syncthreads();

    // ---- outputs: [z_q | z_q_neighbors | q | bmu] ----
    const size_t NBOFF  = (size_t)NROWS * 256;
    const size_t QOFF   = (size_t)NROWS * 1536;
    const size_t BMUOFF = (size_t)NROWS * 1792;

    // q: coalesced STG.64 (lanes cover contiguous node pairs)
    #pragma unroll
    for (int r = 0; r < 8; r++) {
        int row = r0 + r;
        float rq = rqs[row];
        u64* dst = (u64*)(out + QOFF + (size_t)(R0 + row) * NNODES + 2 * cg);
        #pragma unroll
        for (int m = 0; m < 4; m++) {
            u64 av = acc[r][m];
            float ql = fmaf(__uint_as_float((unsigned)av),        rq, EPSF);
            float qh = fmaf(__uint_as_float((unsigned)(av >> 32)), rq, EPSF);
            dst[32 * m] = packf2(ql, qh);
        }
    }

    if (t < TM) out[BMUOFF + R0 + t] = (float)bmuS[t];

    // z_q + neighbor gathers: 6 copies/row, one warp per copy, 16 warps
    const int lane = t & 31, wid = t >> 5;
    for (int cp = wid; cp < TM * 6; cp += 16) {
        int row = cp / 6;
        int s   = cp - row * 6;
        int b   = bmuS[row];
        int idx;
        if (s <= 1) {
            idx = b;
        } else {
            int k1 = b >> 4, k2 = b & 15;
            if      (s == 2) idx = (((k1 + 15) & 15) << 4) + k2;   // up
            else if (s == 3) idx = (((k1 + 1)  & 15) << 4) + k2;   // down
            else if (s == 4) idx = (k1 << 4) + ((k2 + 1)  & 15);   // right
            else             idx = (k1 << 4) + ((k2 + 15) & 15);   // left
        }
        const float4* src = (const float4*)(E + (size_t)idx * LATENT);
        float4 a0 = src[lane], a1 = src[lane + 32];
        float* dstp = (s == 0)
            ? out + (size_t)(R0 + row) * LATENT
            : out + NBOFF + ((size_t)(R0 + row) * 5 + (s - 1)) * LATENT;
        float4* d4 = (float4*)dstp;
        d4[lane]      = a0;
        d4[lane + 32] = a1;
    }
}

extern "C" void kernel_launch(void* const* d_in, const int* in_sizes, int n_in,
                              void* d_out, int out_size) {
    const float* Z = (const float*)d_in[0];
    const float* E = (const float*)d_in[1];
    const int*   A = (const int*)d_in[2];
    float* out = (float*)d_out;

    cudaFuncSetAttribute(som_kernel, cudaFuncAttributeMaxDynamicSharedMemorySize, SMEM_BYTES);
    som_kernel<<<NROWS / TM, NT, SMEM_BYTES>>>(Z, E, A, out);
}